// round 3
// baseline (speedup 1.0000x reference)
#include <cuda_runtime.h>
#include <cstdint>
#include <math.h>

#define CC 1024
#define NROWS (256*1024)
#define RP1 260     // f1 transposed row pad (256 rows + 4)
#define RP2 132     // f2 transposed row pad (128 rows + 4)

typedef unsigned long long ull;

// Scratch (allocation-free rule: __device__ globals)
__device__ float g_adj[2*CC];
__device__ float g_kcbase[2*CC*64];                 // per-(k,c) folded kc@Wn1_kc + bn1
__device__ float g_mnext[(size_t)NROWS * 64];       // 64 MB intermediate m_next

// ---- packed f32x2 helpers -------------------------------------------------
__device__ __forceinline__ ull dup2(float x){ ull r; asm("mov.b64 %0,{%1,%1};":"=l"(r):"f"(x)); return r; }
__device__ __forceinline__ ull pk2(float lo, float hi){ ull r; asm("mov.b64 %0,{%1,%2};":"=l"(r):"f"(lo),"f"(hi)); return r; }
__device__ __forceinline__ float2 up2(ull v){ float2 f; asm("mov.b64 {%0,%1},%2;":"=f"(f.x),"=f"(f.y):"l"(v)); return f; }
__device__ __forceinline__ void fma2(ull&d, ull a, ull b){ asm("fma.rn.f32x2 %0,%1,%2,%0;":"+l"(d):"l"(a),"l"(b)); }

__device__ __forceinline__ float clampf(float v,float lo,float hi){ return fminf(fmaxf(v,lo),hi); }
__device__ __forceinline__ float sigf(float x){ return __fdividef(1.f, 1.f + __expf(-x)); }
__device__ __forceinline__ float tanhfast(float x){
    float t = __expf(-2.f*fabsf(x));
    float r = __fdividef(1.f - t, 1.f + t);
    return copysignf(r, x);
}

// ---------------------------------------------------------------------------
// adj: mask0 has ~5 nonzeros -> compact + gather
// ---------------------------------------------------------------------------
__global__ void adj_kernel(const int* __restrict__ qt,
                           const float* __restrict__ oh,
                           const float* __restrict__ graphs)
{
    __shared__ int   s_idx[CC];
    __shared__ float s_val[CC];
    __shared__ int   s_cnt;
    __shared__ float s_sum;

    int t = threadIdx.x;
    if (t == 0) { s_cnt = 0; s_sum = 0.f; }
    __syncthreads();

    int q0 = qt[0];
    float m = oh[(size_t)q0 * CC + t];
    if (m != 0.f) {
        int p = atomicAdd(&s_cnt, 1);
        s_idx[p] = t; s_val[p] = m;
        atomicAdd(&s_sum, m);
    }
    __syncthreads();

    float denom = fmaxf(s_sum, 1.f);
    int nnz = s_cnt;
    for (int k = 0; k < 2; k++) {
        float acc = 0.f;
        for (int i = 0; i < nnz; i++)
            acc += s_val[i] * graphs[(size_t)k*CC*CC + (size_t)s_idx[i]*CC + t];
        g_adj[k*CC + t] = clampf(acc / denom, -5.f, 5.f);
    }
}

// ---------------------------------------------------------------------------
// kcbase[k][c][j] = bn1[k][j] + sum_e clip(kc[c][e],±5) * Wn1[k][192+e][j]
// ---------------------------------------------------------------------------
__global__ void kcbase_kernel(const float* __restrict__ kc,
                              const float* __restrict__ Wn1,
                              const float* __restrict__ bn1)
{
    __shared__ float skc[64];
    int c = blockIdx.x;
    int tid = threadIdx.x;              // 128
    if (tid < 64) skc[tid] = clampf(kc[c*64 + tid], -5.f, 5.f);
    __syncthreads();
    int k = tid >> 6, j = tid & 63;
    float a = bn1[k*64 + j];
    const float* Wp = Wn1 + k*16384 + 12288 + j;   // rows 192..255 of Wn1[k]
    #pragma unroll 8
    for (int e = 0; e < 64; e++) a = fmaf(skc[e], Wp[e*64], a);
    g_kcbase[((size_t)k*CC + c)*64 + j] = a;
}

// ---------------------------------------------------------------------------
// f1: m_next. 256-row tiles, 8 rows x 8 cols per thread, col-pair FFMA2.
// ---------------------------------------------------------------------------
__global__ void __launch_bounds__(256) f1_kernel(
    const int*   __restrict__ qt,  const float* __restrict__ ht,
    const float* __restrict__ oh,  const float* __restrict__ kc,
    const float* __restrict__ nwp,
    const float* __restrict__ Ws1, const float* __restrict__ bs1,
    const float* __restrict__ Ws2, const float* __restrict__ bs2,
    const float* __restrict__ Wn1, const float* __restrict__ Wn2,
    const float* __restrict__ bn2)
{
    extern __shared__ float sm[];
    float* sWn1 = sm;             // 8192 (ht-part rows 128..191, both k)
    float* sWn2 = sWn1 + 8192;    // 8192
    float* sbn2 = sWn2 + 8192;    // 128
    float* U_T  = sbn2 + 128;     // 64*260 = 16640
    float* H1_T = U_T  + 16640;   // 16640
    float* rmask= H1_T + 16640;   // 256
    float* radj = rmask + 256;    // 512
    float* xr   = radj + 512;     // 128 (masked-row scratch)
    float* hb   = xr + 128;       // 64
    __shared__ int s_mcnt;
    __shared__ int s_mrows[256];

    int tid = threadIdx.x;
    for (int i = tid; i < 8192; i += 256) {
        int k = i >> 12, rc = i & 4095;
        sWn1[i] = Wn1[k*16384 + 8192 + rc];   // rows 128..191 (ht part)
        sWn2[i] = Wn2[i];
    }
    if (tid < 128) sbn2[tid] = bn2[tid];
    float w = clampf(nwp[0], 0.1f, 0.9f);
    __syncthreads();

    int tr = tid >> 3, tc = tid & 7;
    int rbase = tr * 8, cbase = tc * 8;

    for (int tile = blockIdx.x; tile < NROWS/256; tile += gridDim.x) {
        int row0 = tile << 8;
        int c0 = row0 & 1023;
        if (tid == 0) s_mcnt = 0;
        __syncthreads();

        // U_T = clip(ht)^T  (float4 coalesced LDG, scalar transposed STS)
        for (int i = tid; i < 256*16; i += 256) {
            int r = i >> 4, q = i & 15;
            float4 v = *(const float4*)(ht + (size_t)(row0+r)*64 + q*4);
            U_T[(q*4+0)*RP1 + r] = clampf(v.x, -5.f, 5.f);
            U_T[(q*4+1)*RP1 + r] = clampf(v.y, -5.f, 5.f);
            U_T[(q*4+2)*RP1 + r] = clampf(v.z, -5.f, 5.f);
            U_T[(q*4+3)*RP1 + r] = clampf(v.w, -5.f, 5.f);
        }
        {
            int gid = row0 + tid; int b = gid >> 10; int c = gid & 1023;
            float m = oh[(size_t)qt[b]*CC + c];
            rmask[tid] = m;
            radj[tid]       = g_adj[c];
            radj[256 + tid] = g_adj[CC + c];
            if (m > 0.5f) { int p = atomicAdd(&s_mcnt, 1); s_mrows[p] = tid; }
        }
        __syncthreads();

        float nf[8][8];
        #pragma unroll
        for (int k = 0; k < 2; k++) {
            // Stage A: H1 = relu(kcbase + clip(ht) @ Wn1_ht[k])
            ull acc[8][4];
            const float* kcb = g_kcbase + ((size_t)k*CC + c0 + rbase)*64 + cbase;
            #pragma unroll
            for (int i = 0; i < 8; i++) {
                float4 a = *(const float4*)(kcb + i*64);
                float4 b = *(const float4*)(kcb + i*64 + 4);
                acc[i][0]=pk2(a.x,a.y); acc[i][1]=pk2(a.z,a.w);
                acc[i][2]=pk2(b.x,b.y); acc[i][3]=pk2(b.z,b.w);
            }
            {
                const float* Wk = sWn1 + k*4096 + cbase;
                #pragma unroll 8
                for (int kk = 0; kk < 64; kk++) {
                    ulonglong2 w01 = *(const ulonglong2*)(Wk + kk*64);
                    ulonglong2 w23 = *(const ulonglong2*)(Wk + kk*64 + 4);
                    float4 u0 = *(const float4*)(U_T + kk*RP1 + rbase);
                    float4 u1 = *(const float4*)(U_T + kk*RP1 + rbase + 4);
                    ull d;
                    d=dup2(u0.x); fma2(acc[0][0],d,w01.x); fma2(acc[0][1],d,w01.y); fma2(acc[0][2],d,w23.x); fma2(acc[0][3],d,w23.y);
                    d=dup2(u0.y); fma2(acc[1][0],d,w01.x); fma2(acc[1][1],d,w01.y); fma2(acc[1][2],d,w23.x); fma2(acc[1][3],d,w23.y);
                    d=dup2(u0.z); fma2(acc[2][0],d,w01.x); fma2(acc[2][1],d,w01.y); fma2(acc[2][2],d,w23.x); fma2(acc[2][3],d,w23.y);
                    d=dup2(u0.w); fma2(acc[3][0],d,w01.x); fma2(acc[3][1],d,w01.y); fma2(acc[3][2],d,w23.x); fma2(acc[3][3],d,w23.y);
                    d=dup2(u1.x); fma2(acc[4][0],d,w01.x); fma2(acc[4][1],d,w01.y); fma2(acc[4][2],d,w23.x); fma2(acc[4][3],d,w23.y);
                    d=dup2(u1.y); fma2(acc[5][0],d,w01.x); fma2(acc[5][1],d,w01.y); fma2(acc[5][2],d,w23.x); fma2(acc[5][3],d,w23.y);
                    d=dup2(u1.z); fma2(acc[6][0],d,w01.x); fma2(acc[6][1],d,w01.y); fma2(acc[6][2],d,w23.x); fma2(acc[6][3],d,w23.y);
                    d=dup2(u1.w); fma2(acc[7][0],d,w01.x); fma2(acc[7][1],d,w01.y); fma2(acc[7][2],d,w23.x); fma2(acc[7][3],d,w23.y);
                }
            }
            // relu + transpose to H1_T (per-col float4 over row blocks)
            {
                float hc[8][8];
                #pragma unroll
                for (int i = 0; i < 8; i++)
                    #pragma unroll
                    for (int q = 0; q < 4; q++) {
                        float2 v = up2(acc[i][q]);
                        hc[2*q][i]   = fmaxf(v.x, 0.f);
                        hc[2*q+1][i] = fmaxf(v.y, 0.f);
                    }
                #pragma unroll
                for (int c = 0; c < 8; c++) {
                    float4 lo = make_float4(hc[c][0], hc[c][1], hc[c][2], hc[c][3]);
                    float4 hi = make_float4(hc[c][4], hc[c][5], hc[c][6], hc[c][7]);
                    *(float4*)(H1_T + (cbase+c)*RP1 + rbase)     = lo;
                    *(float4*)(H1_T + (cbase+c)*RP1 + rbase + 4) = hi;
                }
            }
            __syncthreads();

            // Stage B: nb = clamp(H1 @ Wn2[k] + bn2[k], 0, 5) -> fold into nf
            {
                const float* bb = sbn2 + k*64 + cbase;
                float4 a = *(const float4*)(bb);
                float4 b = *(const float4*)(bb + 4);
                ull b0=pk2(a.x,a.y), b1=pk2(a.z,a.w), b2=pk2(b.x,b.y), b3=pk2(b.z,b.w);
                #pragma unroll
                for (int i = 0; i < 8; i++) { acc[i][0]=b0; acc[i][1]=b1; acc[i][2]=b2; acc[i][3]=b3; }
            }
            {
                const float* Wk = sWn2 + k*4096 + cbase;
                #pragma unroll 8
                for (int kk = 0; kk < 64; kk++) {
                    ulonglong2 w01 = *(const ulonglong2*)(Wk + kk*64);
                    ulonglong2 w23 = *(const ulonglong2*)(Wk + kk*64 + 4);
                    float4 u0 = *(const float4*)(H1_T + kk*RP1 + rbase);
                    float4 u1 = *(const float4*)(H1_T + kk*RP1 + rbase + 4);
                    ull d;
                    d=dup2(u0.x); fma2(acc[0][0],d,w01.x); fma2(acc[0][1],d,w01.y); fma2(acc[0][2],d,w23.x); fma2(acc[0][3],d,w23.y);
                    d=dup2(u0.y); fma2(acc[1][0],d,w01.x); fma2(acc[1][1],d,w01.y); fma2(acc[1][2],d,w23.x); fma2(acc[1][3],d,w23.y);
                    d=dup2(u0.z); fma2(acc[2][0],d,w01.x); fma2(acc[2][1],d,w01.y); fma2(acc[2][2],d,w23.x); fma2(acc[2][3],d,w23.y);
                    d=dup2(u0.w); fma2(acc[3][0],d,w01.x); fma2(acc[3][1],d,w01.y); fma2(acc[3][2],d,w23.x); fma2(acc[3][3],d,w23.y);
                    d=dup2(u1.x); fma2(acc[4][0],d,w01.x); fma2(acc[4][1],d,w01.y); fma2(acc[4][2],d,w23.x); fma2(acc[4][3],d,w23.y);
                    d=dup2(u1.y); fma2(acc[5][0],d,w01.x); fma2(acc[5][1],d,w01.y); fma2(acc[5][2],d,w23.x); fma2(acc[5][3],d,w23.y);
                    d=dup2(u1.z); fma2(acc[6][0],d,w01.x); fma2(acc[6][1],d,w01.y); fma2(acc[6][2],d,w23.x); fma2(acc[6][3],d,w23.y);
                    d=dup2(u1.w); fma2(acc[7][0],d,w01.x); fma2(acc[7][1],d,w01.y); fma2(acc[7][2],d,w23.x); fma2(acc[7][3],d,w23.y);
                }
            }
            #pragma unroll
            for (int i = 0; i < 8; i++) {
                float a = radj[k*256 + rbase + i];
                #pragma unroll
                for (int q = 0; q < 4; q++) {
                    float2 v = up2(acc[i][q]);
                    float v0 = a * clampf(v.x, 0.f, 5.f);
                    float v1 = a * clampf(v.y, 0.f, 5.f);
                    if (k == 0) {
                        nf[i][2*q]   = clampf(v0, -5.f, 5.f);
                        nf[i][2*q+1] = clampf(v1, -5.f, 5.f);
                    } else {
                        nf[i][2*q]   = clampf(w*nf[i][2*q]   + (1.f-w)*v0, -5.f, 5.f);
                        nf[i][2*q+1] = clampf(w*nf[i][2*q+1] + (1.f-w)*v1, -5.f, 5.f);
                    }
                }
            }
            __syncthreads();   // H1_T free for next k
        }

        // m_next for unmasked rows (|nf|<=5 so the +-50 clamp is identity)
        #pragma unroll
        for (int i = 0; i < 8; i++) {
            int r = rbase + i;
            if (rmask[r] <= 0.5f) {
                float* dst = &g_mnext[(size_t)(row0 + r)*64 + cbase];
                *(float4*)dst       = make_float4(nf[i][0], nf[i][1], nf[i][2], nf[i][3]);
                *(float4*)(dst + 4) = make_float4(nf[i][4], nf[i][5], nf[i][6], nf[i][7]);
            }
        }

        // Rare masked rows: self MLP on RAW [ht, kc] (self_feat in [0,10])
        int mcnt = s_mcnt;
        for (int mi = 0; mi < mcnt; mi++) {
            int r = s_mrows[mi]; int gid = row0 + r; int c = gid & 1023;
            if (tid < 128)
                xr[tid] = (tid < 64) ? ht[(size_t)gid*64 + tid] : kc[c*64 + tid - 64];
            __syncthreads();
            if (tid < 64) {
                float a = bs1[tid];
                for (int j = 0; j < 128; j++) a = fmaf(xr[j], Ws1[j*64 + tid], a);
                hb[tid] = fmaxf(a, 0.f);
            }
            __syncthreads();
            if (tid < 64) {
                float a = bs2[tid];
                for (int j = 0; j < 64; j++) a = fmaf(hb[j], Ws2[j*64 + tid], a);
                g_mnext[(size_t)gid*64 + tid] = clampf(a, 0.f, 10.f);
            }
            __syncthreads();
        }
        __syncthreads();
    }
}

// ---------------------------------------------------------------------------
// f2: edge-gate + fused GRU + head. 128-row tiles, 4 rows x 8 cols per thread.
// X_T[0:64] = m_next^T -> res^T (in place); X_T[64:128] = ht^T.
// ---------------------------------------------------------------------------
__global__ void __launch_bounds__(256) f2_kernel(
    const float* __restrict__ ht,  const float* __restrict__ ea_w,
    const float* __restrict__ We,  const float* __restrict__ be,
    const float* __restrict__ Wa,  const float* __restrict__ ba,
    const float* __restrict__ Wih, const float* __restrict__ bih,
    const float* __restrict__ Whh, const float* __restrict__ bhh,
    const float* __restrict__ Wp,  const float* __restrict__ bp,
    float* __restrict__ out)
{
    extern __shared__ float sm[];
    float* X_T  = sm;             // 128*132 = 16896
    float* sWe  = X_T  + 16896;   // 4096
    float* sWa  = sWe  + 4096;    // 4096
    float* sWrz = sWa  + 4096;    // 16384  ([Wih;Whh] cols 0..127)
    float* sWni = sWrz + 16384;   // 4096
    float* sWnh = sWni + 4096;    // 4096
    float* sbe  = sWnh + 4096;    // 64
    float* sba  = sbe  + 64;      // 64
    float* sbrz = sba  + 64;      // 128
    float* sbni = sbrz + 128;     // 64
    float* sbnh = sbni + 64;      // 64
    float* sWp  = sbnh + 64;      // 64
    float* grow = sWp  + 64;      // 128

    int tid = threadIdx.x;
    for (int i = tid; i < 4096; i += 256) {
        int kk = i >> 6, c = i & 63;
        sWe[i]  = We[i];
        sWa[i]  = Wa[i];
        sWni[i] = Wih[kk*192 + 128 + c];
        sWnh[i] = Whh[kk*192 + 128 + c];
    }
    for (int i = tid; i < 16384; i += 256) {
        int kk = i >> 7, c = i & 127;
        sWrz[i] = (kk < 64) ? Wih[kk*192 + c] : Whh[(kk-64)*192 + c];
    }
    if (tid < 128) sbrz[tid] = bih[tid] + bhh[tid];
    if (tid < 64) {
        sbe[tid] = be[tid]; sba[tid] = ba[tid]; sWp[tid] = Wp[tid];
        sbni[tid] = bih[128+tid]; sbnh[tid] = bhh[128+tid];
    }
    float bpv = bp[0];
    __syncthreads();

    int tr = tid >> 3, tc = tid & 7;
    int rbase = tr * 4, cbase = tc * 8;

    for (int tile = blockIdx.x; tile < NROWS/128; tile += gridDim.x) {
        int row0 = tile << 7;
        for (int i = tid; i < 128*16; i += 256) {
            int r = i >> 4, q = i & 15;
            float4 m4 = *(const float4*)(g_mnext + (size_t)(row0+r)*64 + q*4);
            float4 h4 = *(const float4*)(ht      + (size_t)(row0+r)*64 + q*4);
            X_T[(q*4+0)*RP2 + r] = m4.x; X_T[(q*4+1)*RP2 + r] = m4.y;
            X_T[(q*4+2)*RP2 + r] = m4.z; X_T[(q*4+3)*RP2 + r] = m4.w;
            X_T[(64+q*4+0)*RP2 + r] = h4.x; X_T[(64+q*4+1)*RP2 + r] = h4.y;
            X_T[(64+q*4+2)*RP2 + r] = h4.z; X_T[(64+q*4+3)*RP2 + r] = h4.w;
        }
        if (tid < 128) grow[tid] = ea_w[(row0 + tid) & 1023];
        __syncthreads();

        // Phase A: S=M@We+be, T=M@Wa+ba  (4 rows x 4 col-pairs each)
        ull aS[4][4], aT[4][4];
        {
            float4 e0 = *(const float4*)(sbe + cbase);
            float4 e1 = *(const float4*)(sbe + cbase + 4);
            float4 a0 = *(const float4*)(sba + cbase);
            float4 a1 = *(const float4*)(sba + cbase + 4);
            ull s0=pk2(e0.x,e0.y), s1=pk2(e0.z,e0.w), s2=pk2(e1.x,e1.y), s3=pk2(e1.z,e1.w);
            ull t0=pk2(a0.x,a0.y), t1=pk2(a0.z,a0.w), t2=pk2(a1.x,a1.y), t3=pk2(a1.z,a1.w);
            #pragma unroll
            for (int i = 0; i < 4; i++) {
                aS[i][0]=s0; aS[i][1]=s1; aS[i][2]=s2; aS[i][3]=s3;
                aT[i][0]=t0; aT[i][1]=t1; aT[i][2]=t2; aT[i][3]=t3;
            }
        }
        #pragma unroll 8
        for (int kk = 0; kk < 64; kk++) {
            float4 x4 = *(const float4*)(X_T + kk*RP2 + rbase);
            ull x0=dup2(x4.x), x1=dup2(x4.y), x2=dup2(x4.z), x3=dup2(x4.w);
            ulonglong2 we01 = *(const ulonglong2*)(sWe + kk*64 + cbase);
            ulonglong2 we23 = *(const ulonglong2*)(sWe + kk*64 + cbase + 4);
            ulonglong2 wa01 = *(const ulonglong2*)(sWa + kk*64 + cbase);
            ulonglong2 wa23 = *(const ulonglong2*)(sWa + kk*64 + cbase + 4);
            fma2(aS[0][0],x0,we01.x); fma2(aS[0][1],x0,we01.y); fma2(aS[0][2],x0,we23.x); fma2(aS[0][3],x0,we23.y);
            fma2(aS[1][0],x1,we01.x); fma2(aS[1][1],x1,we01.y); fma2(aS[1][2],x1,we23.x); fma2(aS[1][3],x1,we23.y);
            fma2(aS[2][0],x2,we01.x); fma2(aS[2][1],x2,we01.y); fma2(aS[2][2],x2,we23.x); fma2(aS[2][3],x2,we23.y);
            fma2(aS[3][0],x3,we01.x); fma2(aS[3][1],x3,we01.y); fma2(aS[3][2],x3,we23.x); fma2(aS[3][3],x3,we23.y);
            fma2(aT[0][0],x0,wa01.x); fma2(aT[0][1],x0,wa01.y); fma2(aT[0][2],x0,wa23.x); fma2(aT[0][3],x0,wa23.y);
            fma2(aT[1][0],x1,wa01.x); fma2(aT[1][1],x1,wa01.y); fma2(aT[1][2],x1,wa23.x); fma2(aT[1][3],x1,wa23.y);
            fma2(aT[2][0],x2,wa01.x); fma2(aT[2][1],x2,wa01.y); fma2(aT[2][2],x2,wa23.x); fma2(aT[2][3],x2,wa23.y);
            fma2(aT[3][0],x3,wa01.x); fma2(aT[3][1],x3,wa01.y); fma2(aT[3][2],x3,wa23.x); fma2(aT[3][3],x3,wa23.y);
        }
        __syncthreads();   // all GEMM reads of M done
        #pragma unroll
        for (int i = 0; i < 4; i++) {
            int r = rbase + i; float g = grow[r];
            #pragma unroll
            for (int q = 0; q < 4; q++) {
                float2 s = up2(aS[i][q]);
                float2 t = up2(aT[i][q]);
                int c = cbase + 2*q;
                float m0 = X_T[c*RP2 + r], m1 = X_T[(c+1)*RP2 + r];
                X_T[c*RP2 + r]     = m0 - g*sigf(s.x)*m0 + g*tanhfast(t.x);
                X_T[(c+1)*RP2 + r] = m1 - g*sigf(s.y)*m1 + g*tanhfast(t.y);
            }
        }
        __syncthreads();

        // Phase B: fused r/z over K=128 ([res;ht] @ [Wih;Whh] cols 0..127)
        ull aR[4][4], aZ[4][4];
        {
            float4 r0 = *(const float4*)(sbrz + cbase);
            float4 r1 = *(const float4*)(sbrz + cbase + 4);
            float4 z0 = *(const float4*)(sbrz + 64 + cbase);
            float4 z1 = *(const float4*)(sbrz + 64 + cbase + 4);
            ull br0=pk2(r0.x,r0.y), br1=pk2(r0.z,r0.w), br2=pk2(r1.x,r1.y), br3=pk2(r1.z,r1.w);
            ull bz0=pk2(z0.x,z0.y), bz1=pk2(z0.z,z0.w), bz2=pk2(z1.x,z1.y), bz3=pk2(z1.z,z1.w);
            #pragma unroll
            for (int i = 0; i < 4; i++) {
                aR[i][0]=br0; aR[i][1]=br1; aR[i][2]=br2; aR[i][3]=br3;
                aZ[i][0]=bz0; aZ[i][1]=bz1; aZ[i][2]=bz2; aZ[i][3]=bz3;
            }
        }
        #pragma unroll 8
        for (int kk = 0; kk < 128; kk++) {
            float4 x4 = *(const float4*)(X_T + kk*RP2 + rbase);
            ull x0=dup2(x4.x), x1=dup2(x4.y), x2=dup2(x4.z), x3=dup2(x4.w);
            ulonglong2 wr01 = *(const ulonglong2*)(sWrz + kk*128 + cbase);
            ulonglong2 wr23 = *(const ulonglong2*)(sWrz + kk*128 + cbase + 4);
            ulonglong2 wz01 = *(const ulonglong2*)(sWrz + kk*128 + 64 + cbase);
            ulonglong2 wz23 = *(const ulonglong2*)(sWrz + kk*128 + 64 + cbase + 4);
            fma2(aR[0][0],x0,wr01.x); fma2(aR[0][1],x0,wr01.y); fma2(aR[0][2],x0,wr23.x); fma2(aR[0][3],x0,wr23.y);
            fma2(aR[1][0],x1,wr01.x); fma2(aR[1][1],x1,wr01.y); fma2(aR[1][2],x1,wr23.x); fma2(aR[1][3],x1,wr23.y);
            fma2(aR[2][0],x2,wr01.x); fma2(aR[2][1],x2,wr01.y); fma2(aR[2][2],x2,wr23.x); fma2(aR[2][3],x2,wr23.y);
            fma2(aR[3][0],x3,wr01.x); fma2(aR[3][1],x3,wr01.y); fma2(aR[3][2],x3,wr23.x); fma2(aR[3][3],x3,wr23.y);
            fma2(aZ[0][0],x0,wz01.x); fma2(aZ[0][1],x0,wz01.y); fma2(aZ[0][2],x0,wz23.x); fma2(aZ[0][3],x0,wz23.y);
            fma2(aZ[1][0],x1,wz01.x); fma2(aZ[1][1],x1,wz01.y); fma2(aZ[1][2],x1,wz23.x); fma2(aZ[1][3],x1,wz23.y);
            fma2(aZ[2][0],x2,wz01.x); fma2(aZ[2][1],x2,wz01.y); fma2(aZ[2][2],x2,wz23.x); fma2(aZ[2][3],x2,wz23.y);
            fma2(aZ[3][0],x3,wz01.x); fma2(aZ[3][1],x3,wz01.y); fma2(aZ[3][2],x3,wz23.x); fma2(aZ[3][3],x3,wz23.y);
        }
        float rg[4][8], zg[4][8];
        #pragma unroll
        for (int i = 0; i < 4; i++)
            #pragma unroll
            for (int q = 0; q < 4; q++) {
                float2 vr = up2(aR[i][q]);
                float2 vz = up2(aZ[i][q]);
                rg[i][2*q] = sigf(vr.x); rg[i][2*q+1] = sigf(vr.y);
                zg[i][2*q] = sigf(vz.x); zg[i][2*q+1] = sigf(vz.y);
            }

        // Phase C: n gate (in_ from res, hn from ht), h_next, y
        ull aI[4][4], aH[4][4];
        {
            float4 i0 = *(const float4*)(sbni + cbase);
            float4 i1 = *(const float4*)(sbni + cbase + 4);
            float4 h0 = *(const float4*)(sbnh + cbase);
            float4 h1 = *(const float4*)(sbnh + cbase + 4);
            ull bi0=pk2(i0.x,i0.y), bi1=pk2(i0.z,i0.w), bi2=pk2(i1.x,i1.y), bi3=pk2(i1.z,i1.w);
            ull bh0=pk2(h0.x,h0.y), bh1=pk2(h0.z,h0.w), bh2=pk2(h1.x,h1.y), bh3=pk2(h1.z,h1.w);
            #pragma unroll
            for (int i = 0; i < 4; i++) {
                aI[i][0]=bi0; aI[i][1]=bi1; aI[i][2]=bi2; aI[i][3]=bi3;
                aH[i][0]=bh0; aH[i][1]=bh1; aH[i][2]=bh2; aH[i][3]=bh3;
            }
        }
        #pragma unroll 8
        for (int kk = 0; kk < 64; kk++) {
            float4 x4 = *(const float4*)(X_T + kk*RP2 + rbase);
            ull x0=dup2(x4.x), x1=dup2(x4.y), x2=dup2(x4.z), x3=dup2(x4.w);
            ulonglong2 wi01 = *(const ulonglong2*)(sWni + kk*64 + cbase);
            ulonglong2 wi23 = *(const ulonglong2*)(sWni + kk*64 + cbase + 4);
            fma2(aI[0][0],x0,wi01.x); fma2(aI[0][1],x0,wi01.y); fma2(aI[0][2],x0,wi23.x); fma2(aI[0][3],x0,wi23.y);
            fma2(aI[1][0],x1,wi01.x); fma2(aI[1][1],x1,wi01.y); fma2(aI[1][2],x1,wi23.x); fma2(aI[1][3],x1,wi23.y);
            fma2(aI[2][0],x2,wi01.x); fma2(aI[2][1],x2,wi01.y); fma2(aI[2][2],x2,wi23.x); fma2(aI[2][3],x2,wi23.y);
            fma2(aI[3][0],x3,wi01.x); fma2(aI[3][1],x3,wi01.y); fma2(aI[3][2],x3,wi23.x); fma2(aI[3][3],x3,wi23.y);
        }
        #pragma unroll 8
        for (int kk = 0; kk < 64; kk++) {
            float4 h4 = *(const float4*)(X_T + (64+kk)*RP2 + rbase);
            ull h0=dup2(h4.x), h1=dup2(h4.y), h2=dup2(h4.z), h3=dup2(h4.w);
            ulonglong2 wh01 = *(const ulonglong2*)(sWnh + kk*64 + cbase);
            ulonglong2 wh23 = *(const ulonglong2*)(sWnh + kk*64 + cbase + 4);
            fma2(aH[0][0],h0,wh01.x); fma2(aH[0][1],h0,wh01.y); fma2(aH[0][2],h0,wh23.x); fma2(aH[0][3],h0,wh23.y);
            fma2(aH[1][0],h1,wh01.x); fma2(aH[1][1],h1,wh01.y); fma2(aH[1][2],h1,wh23.x); fma2(aH[1][3],h1,wh23.y);
            fma2(aH[2][0],h2,wh01.x); fma2(aH[2][1],h2,wh01.y); fma2(aH[2][2],h2,wh23.x); fma2(aH[2][3],h2,wh23.y);
            fma2(aH[3][0],h3,wh01.x); fma2(aH[3][1],h3,wh01.y); fma2(aH[3][2],h3,wh23.x); fma2(aH[3][3],h3,wh23.y);
        }
        #pragma unroll
        for (int i = 0; i < 4; i++) {
            int r = rbase + i;
            float py = 0.f;
            #pragma unroll
            for (int q = 0; q < 4; q++) {
                float2 vi = up2(aI[i][q]);
                float2 vh = up2(aH[i][q]);
                int c = cbase + 2*q;
                float n0 = tanhfast(vi.x + rg[i][2*q]   * vh.x);
                float n1 = tanhfast(vi.y + rg[i][2*q+1] * vh.y);
                float h0 = X_T[(64+c)*RP2 + r];
                float h1 = X_T[(64+c+1)*RP2 + r];
                float z0 = zg[i][2*q], z1 = zg[i][2*q+1];
                float hn0 = (1.f - z0)*n0 + z0*h0;
                float hn1 = (1.f - z1)*n1 + z1*h1;
                py = fmaf(hn0, sWp[c],   py);
                py = fmaf(hn1, sWp[c+1], py);
            }
            py += __shfl_down_sync(0xffffffffu, py, 4, 8);
            py += __shfl_down_sync(0xffffffffu, py, 2, 8);
            py += __shfl_down_sync(0xffffffffu, py, 1, 8);
            if (tc == 0) out[row0 + r] = sigf(py + bpv);
        }
        __syncthreads();
    }
}

// ---------------------------------------------------------------------------
extern "C" void kernel_launch(void* const* d_in, const int* in_sizes, int n_in,
                              void* d_out, int out_size)
{
    const int*   qt  = (const int*)  d_in[1];
    const float* ht  = (const float*)d_in[2];
    const float* oh  = (const float*)d_in[3];
    const float* kc  = (const float*)d_in[4];
    const float* gr  = (const float*)d_in[5];
    const float* nw  = (const float*)d_in[6];
    const float* Ws1 = (const float*)d_in[7];
    const float* bs1 = (const float*)d_in[8];
    const float* Ws2 = (const float*)d_in[9];
    const float* bs2 = (const float*)d_in[10];
    const float* Wn1 = (const float*)d_in[11];
    const float* bn1 = (const float*)d_in[12];
    const float* Wn2 = (const float*)d_in[13];
    const float* bn2 = (const float*)d_in[14];
    const float* ea  = (const float*)d_in[15];
    const float* We  = (const float*)d_in[16];
    const float* be  = (const float*)d_in[17];
    const float* Wa  = (const float*)d_in[18];
    const float* ba  = (const float*)d_in[19];
    const float* Wih = (const float*)d_in[20];
    const float* bih = (const float*)d_in[21];
    const float* Whh = (const float*)d_in[22];
    const float* bhh = (const float*)d_in[23];
    const float* Wp  = (const float*)d_in[24];
    const float* bp  = (const float*)d_in[25];
    float* out = (float*)d_out;

    int smc = 148;
    if (cudaDeviceGetAttribute(&smc, cudaDevAttrMultiProcessorCount, 0) != cudaSuccess || smc <= 0)
        smc = 148;

    size_t smem1 = (size_t)(8192+8192+128+16640+16640+256+512+128+64) * 4;                // ~203 KB
    size_t smem2 = (size_t)(16896+4096+4096+16384+4096+4096+64+64+128+64+64+64+128) * 4;  // ~201 KB
    cudaFuncSetAttribute(f1_kernel, cudaFuncAttributeMaxDynamicSharedMemorySize, (int)smem1);
    cudaFuncSetAttribute(f2_kernel, cudaFuncAttributeMaxDynamicSharedMemorySize, (int)smem2);

    adj_kernel<<<1, 1024>>>(qt, oh, gr);
    kcbase_kernel<<<1024, 128>>>(kc, Wn1, bn1);
    f1_kernel<<<smc, 256, smem1>>>(qt, ht, oh, kc, nw, Ws1, bs1, Ws2, bs2, Wn1, Wn2, bn2);
    f2_kernel<<<smc, 256, smem2>>>(ht, ea, We, be, Wa, ba, Wih, bih, Whh, bhh, Wp, bp, out);
}

// round 4
// speedup vs baseline: 1.3400x; 1.3400x over previous
#include <cuda_runtime.h>
#include <cstdint>
#include <math.h>

#define CC 1024
#define NROWS (256*1024)
#define RP1 260     // f1 transposed row pad (256 rows + 4)
#define RP2 132     // f2 transposed row pad (128 rows + 4)

typedef unsigned long long ull;

// Scratch (allocation-free rule: __device__ globals)
__device__ float g_adj[2*CC];
__device__ float g_kcbase[2*CC*64];                 // per-(k,c) folded kc@Wn1_kc + bn1
__device__ float g_mnext[(size_t)NROWS * 64];       // 64 MB intermediate m_next

// ---- packed f32x2 helpers -------------------------------------------------
__device__ __forceinline__ ull dup2(float x){ ull r; asm("mov.b64 %0,{%1,%1};":"=l"(r):"f"(x)); return r; }
__device__ __forceinline__ ull pk2(float lo, float hi){ ull r; asm("mov.b64 %0,{%1,%2};":"=l"(r):"f"(lo),"f"(hi)); return r; }
__device__ __forceinline__ float2 up2(ull v){ float2 f; asm("mov.b64 {%0,%1},%2;":"=f"(f.x),"=f"(f.y):"l"(v)); return f; }
__device__ __forceinline__ void fma2(ull&d, ull a, ull b){ asm("fma.rn.f32x2 %0,%1,%2,%0;":"+l"(d):"l"(a),"l"(b)); }

__device__ __forceinline__ float clampf(float v,float lo,float hi){ return fminf(fmaxf(v,lo),hi); }
__device__ __forceinline__ float sigf(float x){ return __fdividef(1.f, 1.f + __expf(-x)); }
__device__ __forceinline__ float tanhfast(float x){
    float t = __expf(-2.f*fabsf(x));
    float r = __fdividef(1.f - t, 1.f + t);
    return copysignf(r, x);
}

// ---------------------------------------------------------------------------
// adj: mask0 has ~5 nonzeros -> compact + gather
// ---------------------------------------------------------------------------
__global__ void adj_kernel(const int* __restrict__ qt,
                           const float* __restrict__ oh,
                           const float* __restrict__ graphs)
{
    __shared__ int   s_idx[CC];
    __shared__ float s_val[CC];
    __shared__ int   s_cnt;
    __shared__ float s_sum;

    int t = threadIdx.x;
    if (t == 0) { s_cnt = 0; s_sum = 0.f; }
    __syncthreads();

    int q0 = qt[0];
    float m = oh[(size_t)q0 * CC + t];
    if (m != 0.f) {
        int p = atomicAdd(&s_cnt, 1);
        s_idx[p] = t; s_val[p] = m;
        atomicAdd(&s_sum, m);
    }
    __syncthreads();

    float denom = fmaxf(s_sum, 1.f);
    int nnz = s_cnt;
    for (int k = 0; k < 2; k++) {
        float acc = 0.f;
        for (int i = 0; i < nnz; i++)
            acc += s_val[i] * graphs[(size_t)k*CC*CC + (size_t)s_idx[i]*CC + t];
        g_adj[k*CC + t] = clampf(acc / denom, -5.f, 5.f);
    }
}

// ---------------------------------------------------------------------------
// kcbase[k][c][j] = bn1[k][j] + sum_e clip(kc[c][e],±5) * Wn1[k][192+e][j]
// ---------------------------------------------------------------------------
__global__ void kcbase_kernel(const float* __restrict__ kc,
                              const float* __restrict__ Wn1,
                              const float* __restrict__ bn1)
{
    __shared__ float skc[64];
    int c = blockIdx.x;
    int tid = threadIdx.x;              // 128
    if (tid < 64) skc[tid] = clampf(kc[c*64 + tid], -5.f, 5.f);
    __syncthreads();
    int k = tid >> 6, j = tid & 63;
    float a = bn1[k*64 + j];
    const float* Wp = Wn1 + k*16384 + 12288 + j;   // rows 192..255 of Wn1[k]
    #pragma unroll 8
    for (int e = 0; e < 64; e++) a = fmaf(skc[e], Wp[e*64], a);
    g_kcbase[((size_t)k*CC + c)*64 + j] = a;
}

// ---------------------------------------------------------------------------
// f1: m_next. 256-row tiles, 512 threads, 8 rows (row-pair packed) x 4 cols.
// ---------------------------------------------------------------------------
__device__ __forceinline__ void gemm64_rp(ull acc[4][4], const float* W, const float* Xt, int rbase)
{
    #pragma unroll 8
    for (int kk = 0; kk < 64; kk++) {
        float4 w4 = *(const float4*)(W + kk*64);
        ull wd0=dup2(w4.x), wd1=dup2(w4.y), wd2=dup2(w4.z), wd3=dup2(w4.w);
        ulonglong2 ua = *(const ulonglong2*)(Xt + kk*RP1 + rbase);
        ulonglong2 ub = *(const ulonglong2*)(Xt + kk*RP1 + rbase + 4);
        fma2(acc[0][0],ua.x,wd0); fma2(acc[0][1],ua.x,wd1); fma2(acc[0][2],ua.x,wd2); fma2(acc[0][3],ua.x,wd3);
        fma2(acc[1][0],ua.y,wd0); fma2(acc[1][1],ua.y,wd1); fma2(acc[1][2],ua.y,wd2); fma2(acc[1][3],ua.y,wd3);
        fma2(acc[2][0],ub.x,wd0); fma2(acc[2][1],ub.x,wd1); fma2(acc[2][2],ub.x,wd2); fma2(acc[2][3],ub.x,wd3);
        fma2(acc[3][0],ub.y,wd0); fma2(acc[3][1],ub.y,wd1); fma2(acc[3][2],ub.y,wd2); fma2(acc[3][3],ub.y,wd3);
    }
}

__global__ void __launch_bounds__(512) f1_kernel(
    const int*   __restrict__ qt,  const float* __restrict__ ht,
    const float* __restrict__ oh,  const float* __restrict__ kc,
    const float* __restrict__ nwp,
    const float* __restrict__ Ws1, const float* __restrict__ bs1,
    const float* __restrict__ Ws2, const float* __restrict__ bs2,
    const float* __restrict__ Wn1, const float* __restrict__ Wn2,
    const float* __restrict__ bn2)
{
    extern __shared__ float sm[];
    float* sWn1 = sm;             // 8192 (ht-part rows 128..191, both k)
    float* sWn2 = sWn1 + 8192;    // 8192
    float* sbn2 = sWn2 + 8192;    // 128
    float* U_T  = sbn2 + 128;     // 64*260 = 16640
    float* H1_T = U_T  + 16640;   // 16640
    float* rmask= H1_T + 16640;   // 256
    float* radj = rmask + 256;    // 512
    float* xr   = radj + 512;     // 128 (masked-row scratch)
    float* hb   = xr + 128;       // 64
    __shared__ int s_mcnt;
    __shared__ int s_mrows[256];

    int tid = threadIdx.x;
    for (int i = tid; i < 8192; i += 512) {
        int k = i >> 12, rc = i & 4095;
        sWn1[i] = Wn1[k*16384 + 8192 + rc];   // rows 128..191 (ht part)
        sWn2[i] = Wn2[i];
    }
    if (tid < 128) sbn2[tid] = bn2[tid];
    float w = clampf(nwp[0], 0.1f, 0.9f);
    __syncthreads();

    int tr = tid >> 4, tc = tid & 15;      // 32 row-groups x 16 col-groups
    int rbase = tr * 8, cbase = tc * 4;

    for (int tile = blockIdx.x; tile < NROWS/256; tile += gridDim.x) {
        int row0 = tile << 8;
        int c0 = row0 & 1023;
        if (tid == 0) s_mcnt = 0;
        __syncthreads();

        // U_T = clip(ht)^T  (float4 coalesced LDG, scalar transposed STS)
        for (int i = tid; i < 256*16; i += 512) {
            int r = i >> 4, q = i & 15;
            float4 v = *(const float4*)(ht + (size_t)(row0+r)*64 + q*4);
            U_T[(q*4+0)*RP1 + r] = clampf(v.x, -5.f, 5.f);
            U_T[(q*4+1)*RP1 + r] = clampf(v.y, -5.f, 5.f);
            U_T[(q*4+2)*RP1 + r] = clampf(v.z, -5.f, 5.f);
            U_T[(q*4+3)*RP1 + r] = clampf(v.w, -5.f, 5.f);
        }
        if (tid < 256) {
            int gid = row0 + tid; int b = gid >> 10; int c = gid & 1023;
            float m = oh[(size_t)qt[b]*CC + c];
            rmask[tid] = m;
            radj[tid]       = g_adj[c];
            radj[256 + tid] = g_adj[CC + c];
            if (m > 0.5f) { int p = atomicAdd(&s_mcnt, 1); s_mrows[p] = tid; }
        }
        __syncthreads();

        float nf[8][4];
        #pragma unroll
        for (int k = 0; k < 2; k++) {
            // Stage A: H1 = relu(kcbase + clip(ht) @ Wn1_ht[k])
            ull acc[4][4];
            const float* kcb = g_kcbase + ((size_t)k*CC + c0 + rbase)*64 + cbase;
            #pragma unroll
            for (int p = 0; p < 4; p++) {
                float4 a = *(const float4*)(kcb + (2*p)*64);
                float4 b = *(const float4*)(kcb + (2*p+1)*64);
                acc[p][0]=pk2(a.x,b.x); acc[p][1]=pk2(a.y,b.y);
                acc[p][2]=pk2(a.z,b.z); acc[p][3]=pk2(a.w,b.w);
            }
            gemm64_rp(acc, sWn1 + k*4096 + cbase, U_T, rbase);
            #pragma unroll
            for (int p = 0; p < 4; p++)
                #pragma unroll
                for (int c = 0; c < 4; c++) {
                    float2 v = up2(acc[p][c]);
                    v.x = fmaxf(v.x, 0.f); v.y = fmaxf(v.y, 0.f);
                    *(float2*)(H1_T + (cbase+c)*RP1 + rbase + 2*p) = v;
                }
            __syncthreads();

            // Stage B: nb = clamp(H1 @ Wn2[k] + bn2[k], 0, 5); fold into nf
            #pragma unroll
            for (int c = 0; c < 4; c++) {
                ull b = dup2(sbn2[k*64 + cbase + c]);
                acc[0][c]=b; acc[1][c]=b; acc[2][c]=b; acc[3][c]=b;
            }
            gemm64_rp(acc, sWn2 + k*4096 + cbase, H1_T, rbase);
            #pragma unroll
            for (int p = 0; p < 4; p++) {
                float a0 = radj[k*256 + rbase + 2*p];
                float a1 = radj[k*256 + rbase + 2*p + 1];
                #pragma unroll
                for (int c = 0; c < 4; c++) {
                    float2 v = up2(acc[p][c]);
                    float v0 = a0 * clampf(v.x, 0.f, 5.f);
                    float v1 = a1 * clampf(v.y, 0.f, 5.f);
                    if (k == 0) {
                        nf[2*p][c]   = clampf(v0, -5.f, 5.f);
                        nf[2*p+1][c] = clampf(v1, -5.f, 5.f);
                    } else {
                        nf[2*p][c]   = clampf(w*nf[2*p][c]   + (1.f-w)*v0, -5.f, 5.f);
                        nf[2*p+1][c] = clampf(w*nf[2*p+1][c] + (1.f-w)*v1, -5.f, 5.f);
                    }
                }
            }
            __syncthreads();   // H1_T free for next k
        }

        // m_next for unmasked rows (|nf|<=5 so +-50 clamp is identity)
        #pragma unroll
        for (int i = 0; i < 8; i++) {
            int r = rbase + i;
            if (rmask[r] <= 0.5f) {
                *(float4*)(&g_mnext[(size_t)(row0 + r)*64 + cbase]) =
                    make_float4(nf[i][0], nf[i][1], nf[i][2], nf[i][3]);
            }
        }

        // Rare masked rows: self MLP on RAW [ht, kc] (self_feat in [0,10])
        int mcnt = s_mcnt;
        for (int mi = 0; mi < mcnt; mi++) {
            int r = s_mrows[mi]; int gid = row0 + r; int c = gid & 1023;
            if (tid < 128)
                xr[tid] = (tid < 64) ? ht[(size_t)gid*64 + tid] : kc[c*64 + tid - 64];
            __syncthreads();
            if (tid < 64) {
                float a = bs1[tid];
                for (int j = 0; j < 128; j++) a = fmaf(xr[j], Ws1[j*64 + tid], a);
                hb[tid] = fmaxf(a, 0.f);
            }
            __syncthreads();
            if (tid < 64) {
                float a = bs2[tid];
                for (int j = 0; j < 64; j++) a = fmaf(hb[j], Ws2[j*64 + tid], a);
                g_mnext[(size_t)gid*64 + tid] = clampf(a, 0.f, 10.f);
            }
            __syncthreads();
        }
        __syncthreads();
    }
}

// ---------------------------------------------------------------------------
// f2: edge-gate + fused GRU + head. 128-row tiles, 512 threads, 4x4/thread.
// X_T[0:64] = m_next^T -> res^T (in place); X_T[64:128] = ht^T.
// ---------------------------------------------------------------------------
__global__ void __launch_bounds__(512) f2_kernel(
    const float* __restrict__ ht,  const float* __restrict__ ea_w,
    const float* __restrict__ We,  const float* __restrict__ be,
    const float* __restrict__ Wa,  const float* __restrict__ ba,
    const float* __restrict__ Wih, const float* __restrict__ bih,
    const float* __restrict__ Whh, const float* __restrict__ bhh,
    const float* __restrict__ Wp,  const float* __restrict__ bp,
    float* __restrict__ out)
{
    extern __shared__ float sm[];
    float* X_T  = sm;             // 128*132 = 16896
    float* sWe  = X_T  + 16896;   // 4096
    float* sWa  = sWe  + 4096;    // 4096
    float* sWrz = sWa  + 4096;    // 16384  ([Wih;Whh] cols 0..127)
    float* sWni = sWrz + 16384;   // 4096
    float* sWnh = sWni + 4096;    // 4096
    float* sbe  = sWnh + 4096;    // 64
    float* sba  = sbe  + 64;      // 64
    float* sbrz = sba  + 64;      // 128
    float* sbni = sbrz + 128;     // 64
    float* sbnh = sbni + 64;      // 64
    float* sWp  = sbnh + 64;      // 64
    float* grow = sWp  + 64;      // 128

    int tid = threadIdx.x;
    for (int i = tid; i < 4096; i += 512) {
        int kk = i >> 6, c = i & 63;
        sWe[i]  = We[i];
        sWa[i]  = Wa[i];
        sWni[i] = Wih[kk*192 + 128 + c];
        sWnh[i] = Whh[kk*192 + 128 + c];
    }
    for (int i = tid; i < 16384; i += 512) {
        int kk = i >> 7, c = i & 127;
        sWrz[i] = (kk < 64) ? Wih[kk*192 + c] : Whh[(kk-64)*192 + c];
    }
    if (tid < 128) sbrz[tid] = bih[tid] + bhh[tid];
    if (tid < 64) {
        sbe[tid] = be[tid]; sba[tid] = ba[tid]; sWp[tid] = Wp[tid];
        sbni[tid] = bih[128+tid]; sbnh[tid] = bhh[128+tid];
    }
    float bpv = bp[0];
    __syncthreads();

    int tr = tid >> 4, tc = tid & 15;      // 32 row-groups x 16 col-groups
    int rbase = tr * 4, cbase = tc * 4;

    for (int tile = blockIdx.x; tile < NROWS/128; tile += gridDim.x) {
        int row0 = tile << 7;
        for (int i = tid; i < 128*16; i += 512) {
            int r = i >> 4, q = i & 15;
            float4 m4 = *(const float4*)(g_mnext + (size_t)(row0+r)*64 + q*4);
            float4 h4 = *(const float4*)(ht      + (size_t)(row0+r)*64 + q*4);
            X_T[(q*4+0)*RP2 + r] = m4.x; X_T[(q*4+1)*RP2 + r] = m4.y;
            X_T[(q*4+2)*RP2 + r] = m4.z; X_T[(q*4+3)*RP2 + r] = m4.w;
            X_T[(64+q*4+0)*RP2 + r] = h4.x; X_T[(64+q*4+1)*RP2 + r] = h4.y;
            X_T[(64+q*4+2)*RP2 + r] = h4.z; X_T[(64+q*4+3)*RP2 + r] = h4.w;
        }
        if (tid < 128) grow[tid] = ea_w[(row0 + tid) & 1023];
        __syncthreads();

        // Phase A: S=M@We+be, T=M@Wa+ba (col-pair packed)
        ull aS[4][2], aT[4][2];
        {
            ulonglong2 be2 = *(const ulonglong2*)(sbe + cbase);
            ulonglong2 ba2 = *(const ulonglong2*)(sba + cbase);
            #pragma unroll
            for (int i = 0; i < 4; i++) {
                aS[i][0]=be2.x; aS[i][1]=be2.y;
                aT[i][0]=ba2.x; aT[i][1]=ba2.y;
            }
        }
        #pragma unroll 8
        for (int kk = 0; kk < 64; kk++) {
            float4 x4 = *(const float4*)(X_T + kk*RP2 + rbase);
            ull x0=dup2(x4.x), x1=dup2(x4.y), x2=dup2(x4.z), x3=dup2(x4.w);
            ulonglong2 we2 = *(const ulonglong2*)(sWe + kk*64 + cbase);
            ulonglong2 wa2 = *(const ulonglong2*)(sWa + kk*64 + cbase);
            fma2(aS[0][0],x0,we2.x); fma2(aS[0][1],x0,we2.y); fma2(aT[0][0],x0,wa2.x); fma2(aT[0][1],x0,wa2.y);
            fma2(aS[1][0],x1,we2.x); fma2(aS[1][1],x1,we2.y); fma2(aT[1][0],x1,wa2.x); fma2(aT[1][1],x1,wa2.y);
            fma2(aS[2][0],x2,we2.x); fma2(aS[2][1],x2,we2.y); fma2(aT[2][0],x2,wa2.x); fma2(aT[2][1],x2,wa2.y);
            fma2(aS[3][0],x3,we2.x); fma2(aS[3][1],x3,we2.y); fma2(aT[3][0],x3,wa2.x); fma2(aT[3][1],x3,wa2.y);
        }
        __syncthreads();   // all GEMM reads of M done
        #pragma unroll
        for (int i = 0; i < 4; i++) {
            int r = rbase + i; float g = grow[r];
            #pragma unroll
            for (int q = 0; q < 2; q++) {
                float2 s = up2(aS[i][q]);
                float2 t = up2(aT[i][q]);
                int c = cbase + 2*q;
                float m0 = X_T[c*RP2 + r], m1 = X_T[(c+1)*RP2 + r];
                X_T[c*RP2 + r]     = m0 - g*sigf(s.x)*m0 + g*tanhfast(t.x);
                X_T[(c+1)*RP2 + r] = m1 - g*sigf(s.y)*m1 + g*tanhfast(t.y);
            }
        }
        __syncthreads();

        // Phase B: fused r/z gate sums over K=128 ([res;ht] @ [Wih;Whh])
        ull aR[4][2], aZ[4][2];
        {
            ulonglong2 br2 = *(const ulonglong2*)(sbrz + cbase);
            ulonglong2 bz2 = *(const ulonglong2*)(sbrz + 64 + cbase);
            #pragma unroll
            for (int i = 0; i < 4; i++) {
                aR[i][0]=br2.x; aR[i][1]=br2.y;
                aZ[i][0]=bz2.x; aZ[i][1]=bz2.y;
            }
        }
        #pragma unroll 8
        for (int kk = 0; kk < 128; kk++) {
            float4 x4 = *(const float4*)(X_T + kk*RP2 + rbase);
            ull x0=dup2(x4.x), x1=dup2(x4.y), x2=dup2(x4.z), x3=dup2(x4.w);
            ulonglong2 wr2 = *(const ulonglong2*)(sWrz + kk*128 + cbase);
            ulonglong2 wz2 = *(const ulonglong2*)(sWrz + kk*128 + 64 + cbase);
            fma2(aR[0][0],x0,wr2.x); fma2(aR[0][1],x0,wr2.y); fma2(aZ[0][0],x0,wz2.x); fma2(aZ[0][1],x0,wz2.y);
            fma2(aR[1][0],x1,wr2.x); fma2(aR[1][1],x1,wr2.y); fma2(aZ[1][0],x1,wz2.x); fma2(aZ[1][1],x1,wz2.y);
            fma2(aR[2][0],x2,wr2.x); fma2(aR[2][1],x2,wr2.y); fma2(aZ[2][0],x2,wz2.x); fma2(aZ[2][1],x2,wz2.y);
            fma2(aR[3][0],x3,wr2.x); fma2(aR[3][1],x3,wr2.y); fma2(aZ[3][0],x3,wz2.x); fma2(aZ[3][1],x3,wz2.y);
        }
        float rg[4][4], zg[4][4];
        #pragma unroll
        for (int i = 0; i < 4; i++)
            #pragma unroll
            for (int q = 0; q < 2; q++) {
                float2 vr = up2(aR[i][q]);
                float2 vz = up2(aZ[i][q]);
                rg[i][2*q] = sigf(vr.x); rg[i][2*q+1] = sigf(vr.y);
                zg[i][2*q] = sigf(vz.x); zg[i][2*q+1] = sigf(vz.y);
            }

        // Phase C: n gate (in_ from res, hn from ht), h_next, y
        ull aI[4][2], aH[4][2];
        {
            ulonglong2 bi2 = *(const ulonglong2*)(sbni + cbase);
            ulonglong2 bh2 = *(const ulonglong2*)(sbnh + cbase);
            #pragma unroll
            for (int i = 0; i < 4; i++) {
                aI[i][0]=bi2.x; aI[i][1]=bi2.y;
                aH[i][0]=bh2.x; aH[i][1]=bh2.y;
            }
        }
        #pragma unroll 8
        for (int kk = 0; kk < 64; kk++) {
            float4 x4 = *(const float4*)(X_T + kk*RP2 + rbase);
            ull x0=dup2(x4.x), x1=dup2(x4.y), x2=dup2(x4.z), x3=dup2(x4.w);
            ulonglong2 wi2 = *(const ulonglong2*)(sWni + kk*64 + cbase);
            fma2(aI[0][0],x0,wi2.x); fma2(aI[0][1],x0,wi2.y);
            fma2(aI[1][0],x1,wi2.x); fma2(aI[1][1],x1,wi2.y);
            fma2(aI[2][0],x2,wi2.x); fma2(aI[2][1],x2,wi2.y);
            fma2(aI[3][0],x3,wi2.x); fma2(aI[3][1],x3,wi2.y);
        }
        #pragma unroll 8
        for (int kk = 0; kk < 64; kk++) {
            float4 h4 = *(const float4*)(X_T + (64+kk)*RP2 + rbase);
            ull h0=dup2(h4.x), h1=dup2(h4.y), h2=dup2(h4.z), h3=dup2(h4.w);
            ulonglong2 wh2 = *(const ulonglong2*)(sWnh + kk*64 + cbase);
            fma2(aH[0][0],h0,wh2.x); fma2(aH[0][1],h0,wh2.y);
            fma2(aH[1][0],h1,wh2.x); fma2(aH[1][1],h1,wh2.y);
            fma2(aH[2][0],h2,wh2.x); fma2(aH[2][1],h2,wh2.y);
            fma2(aH[3][0],h3,wh2.x); fma2(aH[3][1],h3,wh2.y);
        }
        #pragma unroll
        for (int i = 0; i < 4; i++) {
            int r = rbase + i;
            float py = 0.f;
            #pragma unroll
            for (int q = 0; q < 2; q++) {
                float2 vi = up2(aI[i][q]);
                float2 vh = up2(aH[i][q]);
                int c = cbase + 2*q;
                float n0 = tanhfast(vi.x + rg[i][2*q]   * vh.x);
                float n1 = tanhfast(vi.y + rg[i][2*q+1] * vh.y);
                float h0 = X_T[(64+c)*RP2 + r];
                float h1 = X_T[(64+c+1)*RP2 + r];
                float z0 = zg[i][2*q], z1 = zg[i][2*q+1];
                float hn0 = (1.f - z0)*n0 + z0*h0;
                float hn1 = (1.f - z1)*n1 + z1*h1;
                py = fmaf(hn0, sWp[c],   py);
                py = fmaf(hn1, sWp[c+1], py);
            }
            py += __shfl_down_sync(0xffffffffu, py, 8, 16);
            py += __shfl_down_sync(0xffffffffu, py, 4, 16);
            py += __shfl_down_sync(0xffffffffu, py, 2, 16);
            py += __shfl_down_sync(0xffffffffu, py, 1, 16);
            if (tc == 0) out[row0 + r] = sigf(py + bpv);
        }
        __syncthreads();
    }
}

// ---------------------------------------------------------------------------
extern "C" void kernel_launch(void* const* d_in, const int* in_sizes, int n_in,
                              void* d_out, int out_size)
{
    const int*   qt  = (const int*)  d_in[1];
    const float* ht  = (const float*)d_in[2];
    const float* oh  = (const float*)d_in[3];
    const float* kc  = (const float*)d_in[4];
    const float* gr  = (const float*)d_in[5];
    const float* nw  = (const float*)d_in[6];
    const float* Ws1 = (const float*)d_in[7];
    const float* bs1 = (const float*)d_in[8];
    const float* Ws2 = (const float*)d_in[9];
    const float* bs2 = (const float*)d_in[10];
    const float* Wn1 = (const float*)d_in[11];
    const float* bn1 = (const float*)d_in[12];
    const float* Wn2 = (const float*)d_in[13];
    const float* bn2 = (const float*)d_in[14];
    const float* ea  = (const float*)d_in[15];
    const float* We  = (const float*)d_in[16];
    const float* be  = (const float*)d_in[17];
    const float* Wa  = (const float*)d_in[18];
    const float* ba  = (const float*)d_in[19];
    const float* Wih = (const float*)d_in[20];
    const float* bih = (const float*)d_in[21];
    const float* Whh = (const float*)d_in[22];
    const float* bhh = (const float*)d_in[23];
    const float* Wp  = (const float*)d_in[24];
    const float* bp  = (const float*)d_in[25];
    float* out = (float*)d_out;

    int smc = 148;
    if (cudaDeviceGetAttribute(&smc, cudaDevAttrMultiProcessorCount, 0) != cudaSuccess || smc <= 0)
        smc = 148;

    size_t smem1 = (size_t)(8192+8192+128+16640+16640+256+512+128+64) * 4;                // ~203 KB
    size_t smem2 = (size_t)(16896+4096+4096+16384+4096+4096+64+64+128+64+64+64+128) * 4;  // ~201 KB
    cudaFuncSetAttribute(f1_kernel, cudaFuncAttributeMaxDynamicSharedMemorySize, (int)smem1);
    cudaFuncSetAttribute(f2_kernel, cudaFuncAttributeMaxDynamicSharedMemorySize, (int)smem2);

    adj_kernel<<<1, 1024>>>(qt, oh, gr);
    kcbase_kernel<<<1024, 128>>>(kc, Wn1, bn1);
    f1_kernel<<<smc, 512, smem1>>>(qt, ht, oh, kc, nw, Ws1, bs1, Ws2, bs2, Wn1, Wn2, bn2);
    f2_kernel<<<smc, 512, smem2>>>(ht, ea, We, be, Wa, ba, Wih, bih, Whh, bhh, Wp, bp, out);
}

// round 5
// speedup vs baseline: 1.3873x; 1.0352x over previous
#include <cuda_runtime.h>
#include <cstdint>
#include <math.h>

#define CC 1024
#define NROWS (256*1024)
#define RP1 260     // f1 transposed row pad (256 rows + 4)
#define RP2 132     // f2 transposed row pad (128 rows + 4)

typedef unsigned long long ull;

// Scratch (allocation-free rule: __device__ globals)
__device__ float g_adj[2*CC];
__device__ float g_kcbase[2*CC*64];                 // per-(k,c) folded kc@Wn1_kc + bn1
__device__ float g_mnext[(size_t)NROWS * 64];       // 64 MB intermediate m_next

// ---- packed f32x2 helpers -------------------------------------------------
__device__ __forceinline__ ull dup2(float x){ ull r; asm("mov.b64 %0,{%1,%1};":"=l"(r):"f"(x)); return r; }
__device__ __forceinline__ ull pk2(float lo, float hi){ ull r; asm("mov.b64 %0,{%1,%2};":"=l"(r):"f"(lo),"f"(hi)); return r; }
__device__ __forceinline__ float2 up2(ull v){ float2 f; asm("mov.b64 {%0,%1},%2;":"=f"(f.x),"=f"(f.y):"l"(v)); return f; }
__device__ __forceinline__ void fma2(ull&d, ull a, ull b){ asm("fma.rn.f32x2 %0,%1,%2,%0;":"+l"(d):"l"(a),"l"(b)); }

__device__ __forceinline__ float clampf(float v,float lo,float hi){ return fminf(fmaxf(v,lo),hi); }
__device__ __forceinline__ float sigf(float x){ return __fdividef(1.f, 1.f + __expf(-x)); }
__device__ __forceinline__ float tanhfast(float x){
    float t = __expf(-2.f*fabsf(x));
    float r = __fdividef(1.f - t, 1.f + t);
    return copysignf(r, x);
}

// ---------------------------------------------------------------------------
// adj: mask0 has ~5 nonzeros -> compact + gather
// ---------------------------------------------------------------------------
__global__ void adj_kernel(const int* __restrict__ qt,
                           const float* __restrict__ oh,
                           const float* __restrict__ graphs)
{
    __shared__ int   s_idx[CC];
    __shared__ float s_val[CC];
    __shared__ int   s_cnt;
    __shared__ float s_sum;

    int t = threadIdx.x;
    if (t == 0) { s_cnt = 0; s_sum = 0.f; }
    __syncthreads();

    int q0 = qt[0];
    float m = oh[(size_t)q0 * CC + t];
    if (m != 0.f) {
        int p = atomicAdd(&s_cnt, 1);
        s_idx[p] = t; s_val[p] = m;
        atomicAdd(&s_sum, m);
    }
    __syncthreads();

    float denom = fmaxf(s_sum, 1.f);
    int nnz = s_cnt;
    for (int k = 0; k < 2; k++) {
        float acc = 0.f;
        for (int i = 0; i < nnz; i++)
            acc += s_val[i] * graphs[(size_t)k*CC*CC + (size_t)s_idx[i]*CC + t];
        g_adj[k*CC + t] = clampf(acc / denom, -5.f, 5.f);
    }
}

// ---------------------------------------------------------------------------
// kcbase[k][c][j] = bn1[k][j] + sum_e clip(kc[c][e],±5) * Wn1[k][192+e][j]
// ---------------------------------------------------------------------------
__global__ void kcbase_kernel(const float* __restrict__ kc,
                              const float* __restrict__ Wn1,
                              const float* __restrict__ bn1)
{
    __shared__ float skc[64];
    int c = blockIdx.x;
    int tid = threadIdx.x;              // 128
    if (tid < 64) skc[tid] = clampf(kc[c*64 + tid], -5.f, 5.f);
    __syncthreads();
    int k = tid >> 6, j = tid & 63;
    float a = bn1[k*64 + j];
    const float* Wp = Wn1 + k*16384 + 12288 + j;   // rows 192..255 of Wn1[k]
    #pragma unroll 8
    for (int e = 0; e < 64; e++) a = fmaf(skc[e], Wp[e*64], a);
    g_kcbase[((size_t)k*CC + c)*64 + j] = a;
}

// ---------------------------------------------------------------------------
// f1: m_next. 256-row tiles, 512 threads, 8 rows (row-pair packed) x 4 cols.
// Warp shape: 4 row-groups x 8 col-groups -> balanced LDS traffic.
// ---------------------------------------------------------------------------
__device__ __forceinline__ void gemm64_rp(ull acc[4][4], const float* W, const float* Xt, int rbase)
{
    #pragma unroll 8
    for (int kk = 0; kk < 64; kk++) {
        float4 w4 = *(const float4*)(W + kk*64);
        ull wd0=dup2(w4.x), wd1=dup2(w4.y), wd2=dup2(w4.z), wd3=dup2(w4.w);
        ulonglong2 ua = *(const ulonglong2*)(Xt + kk*RP1 + rbase);
        ulonglong2 ub = *(const ulonglong2*)(Xt + kk*RP1 + rbase + 4);
        fma2(acc[0][0],ua.x,wd0); fma2(acc[0][1],ua.x,wd1); fma2(acc[0][2],ua.x,wd2); fma2(acc[0][3],ua.x,wd3);
        fma2(acc[1][0],ua.y,wd0); fma2(acc[1][1],ua.y,wd1); fma2(acc[1][2],ua.y,wd2); fma2(acc[1][3],ua.y,wd3);
        fma2(acc[2][0],ub.x,wd0); fma2(acc[2][1],ub.x,wd1); fma2(acc[2][2],ub.x,wd2); fma2(acc[2][3],ub.x,wd3);
        fma2(acc[3][0],ub.y,wd0); fma2(acc[3][1],ub.y,wd1); fma2(acc[3][2],ub.y,wd2); fma2(acc[3][3],ub.y,wd3);
    }
}

__global__ void __launch_bounds__(512) f1_kernel(
    const int*   __restrict__ qt,  const float* __restrict__ ht,
    const float* __restrict__ oh,  const float* __restrict__ kc,
    const float* __restrict__ nwp,
    const float* __restrict__ Ws1, const float* __restrict__ bs1,
    const float* __restrict__ Ws2, const float* __restrict__ bs2,
    const float* __restrict__ Wn1, const float* __restrict__ Wn2,
    const float* __restrict__ bn2)
{
    extern __shared__ float sm[];
    float* sWn1 = sm;             // 8192 (ht-part rows 128..191, both k)
    float* sWn2 = sWn1 + 8192;    // 8192
    float* sbn2 = sWn2 + 8192;    // 128
    float* U_T  = sbn2 + 128;     // 64*260 = 16640
    float* H1_T = U_T  + 16640;   // 16640
    float* rmask= H1_T + 16640;   // 256
    float* radj = rmask + 256;    // 512
    float* xr   = radj + 512;     // 128 (masked-row scratch)
    float* hb   = xr + 128;       // 64
    __shared__ int s_mcnt;
    __shared__ int s_mrows[256];

    int tid = threadIdx.x;
    for (int i = tid; i < 8192; i += 512) {
        int k = i >> 12, rc = i & 4095;
        sWn1[i] = Wn1[k*16384 + 8192 + rc];   // rows 128..191 (ht part)
        sWn2[i] = Wn2[i];
    }
    if (tid < 128) sbn2[tid] = bn2[tid];
    float w = clampf(nwp[0], 0.1f, 0.9f);
    __syncthreads();

    int wid = tid >> 5, lane = tid & 31;
    int tr = (wid & 7) * 4 + (lane >> 3);   // 32 row-groups (8 rows each)
    int tc = (wid >> 3) * 8 + (lane & 7);   // 16 col-groups (4 cols each)
    int rbase = tr * 8, cbase = tc * 4;

    for (int tile = blockIdx.x; tile < NROWS/256; tile += gridDim.x) {
        int row0 = tile << 8;
        int c0 = row0 & 1023;
        if (tid == 0) s_mcnt = 0;
        __syncthreads();

        // U_T = clip(ht)^T  (float4 coalesced LDG, scalar transposed STS)
        for (int i = tid; i < 256*16; i += 512) {
            int r = i >> 4, q = i & 15;
            float4 v = *(const float4*)(ht + (size_t)(row0+r)*64 + q*4);
            U_T[(q*4+0)*RP1 + r] = clampf(v.x, -5.f, 5.f);
            U_T[(q*4+1)*RP1 + r] = clampf(v.y, -5.f, 5.f);
            U_T[(q*4+2)*RP1 + r] = clampf(v.z, -5.f, 5.f);
            U_T[(q*4+3)*RP1 + r] = clampf(v.w, -5.f, 5.f);
        }
        if (tid < 256) {
            int gid = row0 + tid; int b = gid >> 10; int c = gid & 1023;
            float m = oh[(size_t)qt[b]*CC + c];
            rmask[tid] = m;
            radj[tid]       = g_adj[c];
            radj[256 + tid] = g_adj[CC + c];
            if (m > 0.5f) { int p = atomicAdd(&s_mcnt, 1); s_mrows[p] = tid; }
        }
        __syncthreads();

        float nf[8][4];
        #pragma unroll
        for (int k = 0; k < 2; k++) {
            // Stage A: H1 = relu(kcbase + clip(ht) @ Wn1_ht[k])
            ull acc[4][4];
            const float* kcb = g_kcbase + ((size_t)k*CC + c0 + rbase)*64 + cbase;
            #pragma unroll
            for (int p = 0; p < 4; p++) {
                float4 a = *(const float4*)(kcb + (2*p)*64);
                float4 b = *(const float4*)(kcb + (2*p+1)*64);
                acc[p][0]=pk2(a.x,b.x); acc[p][1]=pk2(a.y,b.y);
                acc[p][2]=pk2(a.z,b.z); acc[p][3]=pk2(a.w,b.w);
            }
            gemm64_rp(acc, sWn1 + k*4096 + cbase, U_T, rbase);
            #pragma unroll
            for (int p = 0; p < 4; p++)
                #pragma unroll
                for (int c = 0; c < 4; c++) {
                    float2 v = up2(acc[p][c]);
                    v.x = fmaxf(v.x, 0.f); v.y = fmaxf(v.y, 0.f);
                    *(float2*)(H1_T + (cbase+c)*RP1 + rbase + 2*p) = v;
                }
            __syncthreads();

            // Stage B: nb = clamp(H1 @ Wn2[k] + bn2[k], 0, 5); fold into nf
            #pragma unroll
            for (int c = 0; c < 4; c++) {
                ull b = dup2(sbn2[k*64 + cbase + c]);
                acc[0][c]=b; acc[1][c]=b; acc[2][c]=b; acc[3][c]=b;
            }
            gemm64_rp(acc, sWn2 + k*4096 + cbase, H1_T, rbase);
            #pragma unroll
            for (int p = 0; p < 4; p++) {
                float a0 = radj[k*256 + rbase + 2*p];
                float a1 = radj[k*256 + rbase + 2*p + 1];
                #pragma unroll
                for (int c = 0; c < 4; c++) {
                    float2 v = up2(acc[p][c]);
                    float v0 = a0 * clampf(v.x, 0.f, 5.f);
                    float v1 = a1 * clampf(v.y, 0.f, 5.f);
                    if (k == 0) {
                        nf[2*p][c]   = clampf(v0, -5.f, 5.f);
                        nf[2*p+1][c] = clampf(v1, -5.f, 5.f);
                    } else {
                        nf[2*p][c]   = clampf(w*nf[2*p][c]   + (1.f-w)*v0, -5.f, 5.f);
                        nf[2*p+1][c] = clampf(w*nf[2*p+1][c] + (1.f-w)*v1, -5.f, 5.f);
                    }
                }
            }
            __syncthreads();   // H1_T free for next k
        }

        // m_next for unmasked rows (|nf|<=5 so +-50 clamp is identity)
        #pragma unroll
        for (int i = 0; i < 8; i++) {
            int r = rbase + i;
            if (rmask[r] <= 0.5f) {
                *(float4*)(&g_mnext[(size_t)(row0 + r)*64 + cbase]) =
                    make_float4(nf[i][0], nf[i][1], nf[i][2], nf[i][3]);
            }
        }

        // Rare masked rows: self MLP on RAW [ht, kc] (self_feat in [0,10])
        int mcnt = s_mcnt;
        for (int mi = 0; mi < mcnt; mi++) {
            int r = s_mrows[mi]; int gid = row0 + r; int c = gid & 1023;
            if (tid < 128)
                xr[tid] = (tid < 64) ? ht[(size_t)gid*64 + tid] : kc[c*64 + tid - 64];
            __syncthreads();
            if (tid < 64) {
                float a = bs1[tid];
                for (int j = 0; j < 128; j++) a = fmaf(xr[j], Ws1[j*64 + tid], a);
                hb[tid] = fmaxf(a, 0.f);
            }
            __syncthreads();
            if (tid < 64) {
                float a = bs2[tid];
                for (int j = 0; j < 64; j++) a = fmaf(hb[j], Ws2[j*64 + tid], a);
                g_mnext[(size_t)gid*64 + tid] = clampf(a, 0.f, 10.f);
            }
            __syncthreads();
        }
        __syncthreads();
    }
}

// ---------------------------------------------------------------------------
// f2: edge-gate + fused GRU + head. 128-row tiles, 512 threads, 4x4/thread.
// Warp shape: 8 row-groups x 4 col-groups -> balanced LDS traffic.
// X_T[0:64] = m_next^T -> res^T (in place); X_T[64:128] = ht^T.
// ---------------------------------------------------------------------------
__global__ void __launch_bounds__(512) f2_kernel(
    const float* __restrict__ ht,  const float* __restrict__ ea_w,
    const float* __restrict__ We,  const float* __restrict__ be,
    const float* __restrict__ Wa,  const float* __restrict__ ba,
    const float* __restrict__ Wih, const float* __restrict__ bih,
    const float* __restrict__ Whh, const float* __restrict__ bhh,
    const float* __restrict__ Wp,  const float* __restrict__ bp,
    float* __restrict__ out)
{
    extern __shared__ float sm[];
    float* X_T  = sm;             // 128*132 = 16896
    float* sWe  = X_T  + 16896;   // 4096
    float* sWa  = sWe  + 4096;    // 4096
    float* sWrz = sWa  + 4096;    // 16384  ([Wih;Whh] cols 0..127)
    float* sWni = sWrz + 16384;   // 4096
    float* sWnh = sWni + 4096;    // 4096
    float* sbe  = sWnh + 4096;    // 64
    float* sba  = sbe  + 64;      // 64
    float* sbrz = sba  + 64;      // 128
    float* sbni = sbrz + 128;     // 64
    float* sbnh = sbni + 64;      // 64
    float* sWp  = sbnh + 64;      // 64
    float* grow = sWp  + 64;      // 128
    float* sred = grow + 128;     // 512 (4 warp-quads x 128 rows)

    int tid = threadIdx.x;
    for (int i = tid; i < 4096; i += 512) {
        int kk = i >> 6, c = i & 63;
        sWe[i]  = We[i];
        sWa[i]  = Wa[i];
        sWni[i] = Wih[kk*192 + 128 + c];
        sWnh[i] = Whh[kk*192 + 128 + c];
    }
    for (int i = tid; i < 16384; i += 512) {
        int kk = i >> 7, c = i & 127;
        sWrz[i] = (kk < 64) ? Wih[kk*192 + c] : Whh[(kk-64)*192 + c];
    }
    if (tid < 128) sbrz[tid] = bih[tid] + bhh[tid];
    if (tid < 64) {
        sbe[tid] = be[tid]; sba[tid] = ba[tid]; sWp[tid] = Wp[tid];
        sbni[tid] = bih[128+tid]; sbnh[tid] = bhh[128+tid];
    }
    float bpv = bp[0];
    __syncthreads();

    int wid = tid >> 5, lane = tid & 31;
    int tr = (wid & 3) * 8 + (lane >> 2);   // 32 row-groups (4 rows each)
    int tc = (wid >> 2) * 4 + (lane & 3);   // 16 col-groups (4 cols each)
    int rbase = tr * 4, cbase = tc * 4;

    for (int tile = blockIdx.x; tile < NROWS/128; tile += gridDim.x) {
        int row0 = tile << 7;
        for (int i = tid; i < 128*16; i += 512) {
            int r = i >> 4, q = i & 15;
            float4 m4 = *(const float4*)(g_mnext + (size_t)(row0+r)*64 + q*4);
            float4 h4 = *(const float4*)(ht      + (size_t)(row0+r)*64 + q*4);
            X_T[(q*4+0)*RP2 + r] = m4.x; X_T[(q*4+1)*RP2 + r] = m4.y;
            X_T[(q*4+2)*RP2 + r] = m4.z; X_T[(q*4+3)*RP2 + r] = m4.w;
            X_T[(64+q*4+0)*RP2 + r] = h4.x; X_T[(64+q*4+1)*RP2 + r] = h4.y;
            X_T[(64+q*4+2)*RP2 + r] = h4.z; X_T[(64+q*4+3)*RP2 + r] = h4.w;
        }
        if (tid < 128) grow[tid] = ea_w[(row0 + tid) & 1023];
        __syncthreads();

        // Phase A: S=M@We+be, T=M@Wa+ba (col-pair packed)
        ull aS[4][2], aT[4][2];
        {
            ulonglong2 be2 = *(const ulonglong2*)(sbe + cbase);
            ulonglong2 ba2 = *(const ulonglong2*)(sba + cbase);
            #pragma unroll
            for (int i = 0; i < 4; i++) {
                aS[i][0]=be2.x; aS[i][1]=be2.y;
                aT[i][0]=ba2.x; aT[i][1]=ba2.y;
            }
        }
        #pragma unroll 8
        for (int kk = 0; kk < 64; kk++) {
            float4 x4 = *(const float4*)(X_T + kk*RP2 + rbase);
            ull x0=dup2(x4.x), x1=dup2(x4.y), x2=dup2(x4.z), x3=dup2(x4.w);
            ulonglong2 we2 = *(const ulonglong2*)(sWe + kk*64 + cbase);
            ulonglong2 wa2 = *(const ulonglong2*)(sWa + kk*64 + cbase);
            fma2(aS[0][0],x0,we2.x); fma2(aS[0][1],x0,we2.y); fma2(aT[0][0],x0,wa2.x); fma2(aT[0][1],x0,wa2.y);
            fma2(aS[1][0],x1,we2.x); fma2(aS[1][1],x1,we2.y); fma2(aT[1][0],x1,wa2.x); fma2(aT[1][1],x1,wa2.y);
            fma2(aS[2][0],x2,we2.x); fma2(aS[2][1],x2,we2.y); fma2(aT[2][0],x2,wa2.x); fma2(aT[2][1],x2,wa2.y);
            fma2(aS[3][0],x3,we2.x); fma2(aS[3][1],x3,we2.y); fma2(aT[3][0],x3,wa2.x); fma2(aT[3][1],x3,wa2.y);
        }
        __syncthreads();   // all GEMM reads of M done
        #pragma unroll
        for (int i = 0; i < 4; i++) {
            int r = rbase + i; float g = grow[r];
            #pragma unroll
            for (int q = 0; q < 2; q++) {
                float2 s = up2(aS[i][q]);
                float2 t = up2(aT[i][q]);
                int c = cbase + 2*q;
                float m0 = X_T[c*RP2 + r], m1 = X_T[(c+1)*RP2 + r];
                X_T[c*RP2 + r]     = m0 - g*sigf(s.x)*m0 + g*tanhfast(t.x);
                X_T[(c+1)*RP2 + r] = m1 - g*sigf(s.y)*m1 + g*tanhfast(t.y);
            }
        }
        __syncthreads();

        // Phase B: fused r/z gate sums over K=128 ([res;ht] @ [Wih;Whh])
        ull aR[4][2], aZ[4][2];
        {
            ulonglong2 br2 = *(const ulonglong2*)(sbrz + cbase);
            ulonglong2 bz2 = *(const ulonglong2*)(sbrz + 64 + cbase);
            #pragma unroll
            for (int i = 0; i < 4; i++) {
                aR[i][0]=br2.x; aR[i][1]=br2.y;
                aZ[i][0]=bz2.x; aZ[i][1]=bz2.y;
            }
        }
        #pragma unroll 8
        for (int kk = 0; kk < 128; kk++) {
            float4 x4 = *(const float4*)(X_T + kk*RP2 + rbase);
            ull x0=dup2(x4.x), x1=dup2(x4.y), x2=dup2(x4.z), x3=dup2(x4.w);
            ulonglong2 wr2 = *(const ulonglong2*)(sWrz + kk*128 + cbase);
            ulonglong2 wz2 = *(const ulonglong2*)(sWrz + kk*128 + 64 + cbase);
            fma2(aR[0][0],x0,wr2.x); fma2(aR[0][1],x0,wr2.y); fma2(aZ[0][0],x0,wz2.x); fma2(aZ[0][1],x0,wz2.y);
            fma2(aR[1][0],x1,wr2.x); fma2(aR[1][1],x1,wr2.y); fma2(aZ[1][0],x1,wz2.x); fma2(aZ[1][1],x1,wz2.y);
            fma2(aR[2][0],x2,wr2.x); fma2(aR[2][1],x2,wr2.y); fma2(aZ[2][0],x2,wz2.x); fma2(aZ[2][1],x2,wz2.y);
            fma2(aR[3][0],x3,wr2.x); fma2(aR[3][1],x3,wr2.y); fma2(aZ[3][0],x3,wz2.x); fma2(aZ[3][1],x3,wz2.y);
        }
        float rg[4][4], zg[4][4];
        #pragma unroll
        for (int i = 0; i < 4; i++)
            #pragma unroll
            for (int q = 0; q < 2; q++) {
                float2 vr = up2(aR[i][q]);
                float2 vz = up2(aZ[i][q]);
                rg[i][2*q] = sigf(vr.x); rg[i][2*q+1] = sigf(vr.y);
                zg[i][2*q] = sigf(vz.x); zg[i][2*q+1] = sigf(vz.y);
            }

        // Phase C: n gate (in_ from res, hn from ht), h_next, y
        ull aI[4][2], aH[4][2];
        {
            ulonglong2 bi2 = *(const ulonglong2*)(sbni + cbase);
            ulonglong2 bh2 = *(const ulonglong2*)(sbnh + cbase);
            #pragma unroll
            for (int i = 0; i < 4; i++) {
                aI[i][0]=bi2.x; aI[i][1]=bi2.y;
                aH[i][0]=bh2.x; aH[i][1]=bh2.y;
            }
        }
        #pragma unroll 8
        for (int kk = 0; kk < 64; kk++) {
            float4 x4 = *(const float4*)(X_T + kk*RP2 + rbase);
            ull x0=dup2(x4.x), x1=dup2(x4.y), x2=dup2(x4.z), x3=dup2(x4.w);
            ulonglong2 wi2 = *(const ulonglong2*)(sWni + kk*64 + cbase);
            fma2(aI[0][0],x0,wi2.x); fma2(aI[0][1],x0,wi2.y);
            fma2(aI[1][0],x1,wi2.x); fma2(aI[1][1],x1,wi2.y);
            fma2(aI[2][0],x2,wi2.x); fma2(aI[2][1],x2,wi2.y);
            fma2(aI[3][0],x3,wi2.x); fma2(aI[3][1],x3,wi2.y);
        }
        #pragma unroll 8
        for (int kk = 0; kk < 64; kk++) {
            float4 h4 = *(const float4*)(X_T + (64+kk)*RP2 + rbase);
            ull h0=dup2(h4.x), h1=dup2(h4.y), h2=dup2(h4.z), h3=dup2(h4.w);
            ulonglong2 wh2 = *(const ulonglong2*)(sWnh + kk*64 + cbase);
            fma2(aH[0][0],h0,wh2.x); fma2(aH[0][1],h0,wh2.y);
            fma2(aH[1][0],h1,wh2.x); fma2(aH[1][1],h1,wh2.y);
            fma2(aH[2][0],h2,wh2.x); fma2(aH[2][1],h2,wh2.y);
            fma2(aH[3][0],h3,wh2.x); fma2(aH[3][1],h3,wh2.y);
        }
        #pragma unroll
        for (int i = 0; i < 4; i++) {
            int r = rbase + i;
            float py = 0.f;
            #pragma unroll
            for (int q = 0; q < 2; q++) {
                float2 vi = up2(aI[i][q]);
                float2 vh = up2(aH[i][q]);
                int c = cbase + 2*q;
                float n0 = tanhfast(vi.x + rg[i][2*q]   * vh.x);
                float n1 = tanhfast(vi.y + rg[i][2*q+1] * vh.y);
                float h0 = X_T[(64+c)*RP2 + r];
                float h1 = X_T[(64+c+1)*RP2 + r];
                float z0 = zg[i][2*q], z1 = zg[i][2*q+1];
                float hn0 = (1.f - z0)*n0 + z0*h0;
                float hn1 = (1.f - z1)*n1 + z1*h1;
                py = fmaf(hn0, sWp[c],   py);
                py = fmaf(hn1, sWp[c+1], py);
            }
            // sum over the 4 col-groups held by this warp (lanes sharing lane>>2)
            py += __shfl_xor_sync(0xffffffffu, py, 1, 4);
            py += __shfl_xor_sync(0xffffffffu, py, 2, 4);
            if ((lane & 3) == 0) sred[(wid >> 2) * 128 + r] = py;
        }
        __syncthreads();
        if (tid < 128) {
            float y = sred[tid] + sred[128 + tid] + sred[256 + tid] + sred[384 + tid];
            out[row0 + tid] = sigf(y + bpv);
        }
        __syncthreads();
    }
}

// ---------------------------------------------------------------------------
extern "C" void kernel_launch(void* const* d_in, const int* in_sizes, int n_in,
                              void* d_out, int out_size)
{
    const int*   qt  = (const int*)  d_in[1];
    const float* ht  = (const float*)d_in[2];
    const float* oh  = (const float*)d_in[3];
    const float* kc  = (const float*)d_in[4];
    const float* gr  = (const float*)d_in[5];
    const float* nw  = (const float*)d_in[6];
    const float* Ws1 = (const float*)d_in[7];
    const float* bs1 = (const float*)d_in[8];
    const float* Ws2 = (const float*)d_in[9];
    const float* bs2 = (const float*)d_in[10];
    const float* Wn1 = (const float*)d_in[11];
    const float* bn1 = (const float*)d_in[12];
    const float* Wn2 = (const float*)d_in[13];
    const float* bn2 = (const float*)d_in[14];
    const float* ea  = (const float*)d_in[15];
    const float* We  = (const float*)d_in[16];
    const float* be  = (const float*)d_in[17];
    const float* Wa  = (const float*)d_in[18];
    const float* ba  = (const float*)d_in[19];
    const float* Wih = (const float*)d_in[20];
    const float* bih = (const float*)d_in[21];
    const float* Whh = (const float*)d_in[22];
    const float* bhh = (const float*)d_in[23];
    const float* Wp  = (const float*)d_in[24];
    const float* bp  = (const float*)d_in[25];
    float* out = (float*)d_out;

    int smc = 148;
    if (cudaDeviceGetAttribute(&smc, cudaDevAttrMultiProcessorCount, 0) != cudaSuccess || smc <= 0)
        smc = 148;

    size_t smem1 = (size_t)(8192+8192+128+16640+16640+256+512+128+64) * 4;                     // ~203 KB
    size_t smem2 = (size_t)(16896+4096+4096+16384+4096+4096+64+64+128+64+64+64+128+512) * 4;   // ~203 KB
    cudaFuncSetAttribute(f1_kernel, cudaFuncAttributeMaxDynamicSharedMemorySize, (int)smem1);
    cudaFuncSetAttribute(f2_kernel, cudaFuncAttributeMaxDynamicSharedMemorySize, (int)smem2);

    adj_kernel<<<1, 1024>>>(qt, oh, gr);
    kcbase_kernel<<<1024, 128>>>(kc, Wn1, bn1);
    f1_kernel<<<smc, 512, smem1>>>(qt, ht, oh, kc, nw, Ws1, bs1, Ws2, bs2, Wn1, Wn2, bn2);
    f2_kernel<<<smc, 512, smem2>>>(ht, ea, We, be, Wa, ba, Wih, bih, Whh, bhh, Wp, bp, out);
}